// round 4
// baseline (speedup 1.0000x reference)
#include <cuda_runtime.h>
#include <math.h>

#define CCH   256
#define HW    384
#define NPIX  (HW*HW)        // 147456 elems per channel
#define NQ    (NPIX/4)       // 36864 float4 per channel
#define QPR   (HW/4)         // 96 float4 per row
#define NSEG  4
#define ROWS_PER_SEG (HW/NSEG)            // 96 rows
#define ITER  (ROWS_PER_SEG/4)            // 24 iterations per thread
#define INVN  (1.0f/(382.0f*382.0f))

// Partial stats per (input, channel):
// [0]=total, [1..4]=row sums {0,1,382,383}, [5..8]=col sums {0,1,382,383},
// [9..24]=corners [row-class*4 + col-class]
__device__ float g_stat[2][CCH][25];
__device__ float g_S[2][CCH][9];
__device__ float g_cf[2][CCH];

__global__ void init_kernel() {
    int i = blockIdx.x * 256 + threadIdx.x;
    if (i < 2 * CCH * 25) ((float*)g_stat)[i] = 0.0f;
}

// ---------------------------------------------------------------------------
// Kernel 1: partial stats. grid = (CCH, NSEG, 2), block = 384.
// Threads: r0 = tid/96 (row phase), q = tid%96 (column quad).
// Iteration j covers global row seg*96 + 4j + r0.
// Border rows live only in (seg==0, j==0, r0<2) and (seg==3, j==23, r0>=2).
// ---------------------------------------------------------------------------
__global__ void __launch_bounds__(384) stats_kernel(const float* __restrict__ in1,
                                                    const float* __restrict__ in2) {
    const int c     = blockIdx.x;
    const int seg   = blockIdx.y;
    const int which = blockIdx.z;
    const float4* x = ((const float4*)(which ? in2 : in1))
                      + (size_t)c * NQ + (size_t)seg * (ROWS_PER_SEG * QPR);

    const int tid = threadIdx.x;
    const int r0  = tid / 96;
    const int q   = tid - r0 * 96;
    const bool q0  = (q == 0);
    const bool q95 = (q == 95);

    __shared__ float rowsh[4];
    __shared__ float colsh[4];
    __shared__ float red[12];
    if (tid < 4) { rowsh[tid] = 0.0f; colsh[tid] = 0.0f; }
    __syncthreads();

    const float4* p = x + (size_t)(r0 * 96 + q);

    float tot = 0.0f;
    float c0 = 0.0f, c1 = 0.0f, c2 = 0.0f, c3 = 0.0f;
    float accR = 0.0f;    // border-row contribution (row class r0 when seg 0, r0 when seg 3)

    int jstart = 0, jend = ITER;

    if (seg == 0) {
        // peel j = 0 : rows 0..3 -> rows 0,1 are border (r0 < 2)
        float4 v = __ldcs(p);
        float s = (v.x + v.y) + (v.z + v.w);
        tot += s;
        if (q0)  { c0 += v.x; c1 += v.y; }
        if (q95) { c2 += v.z; c3 += v.w; }
        if (r0 < 2) {
            accR += s;
            // corners: row class r0 (0 or 1)
            if (q0)  { g_stat[which][c][9 + r0*4 + 0] = v.x; g_stat[which][c][9 + r0*4 + 1] = v.y; }
            if (q95) { g_stat[which][c][9 + r0*4 + 2] = v.z; g_stat[which][c][9 + r0*4 + 3] = v.w; }
        }
        p += 384;
        jstart = 1;
    }
    if (seg == NSEG - 1) jend = ITER - 1;

    #pragma unroll 4
    for (int j = jstart; j < jend; j++) {
        float4 v = __ldcs(p);
        p += 384;
        tot += (v.x + v.y) + (v.z + v.w);
        if (q0)  { c0 += v.x; c1 += v.y; }
        if (q95) { c2 += v.z; c3 += v.w; }
    }

    if (seg == NSEG - 1) {
        // peel j = 23 : rows 380..383 -> rows 382,383 are border (r0 >= 2)
        float4 v = __ldcs(p);
        float s = (v.x + v.y) + (v.z + v.w);
        tot += s;
        if (q0)  { c0 += v.x; c1 += v.y; }
        if (q95) { c2 += v.z; c3 += v.w; }
        if (r0 >= 2) {
            accR += s;
            // corners: row class r0 (2 or 3 -> rows 382,383)
            if (q0)  { g_stat[which][c][9 + r0*4 + 0] = v.x; g_stat[which][c][9 + r0*4 + 1] = v.y; }
            if (q95) { g_stat[which][c][9 + r0*4 + 2] = v.z; g_stat[which][c][9 + r0*4 + 3] = v.w; }
        }
    }

    // ---- block reductions ----
    if (accR != 0.0f || (seg == 0 && r0 < 2) || (seg == NSEG - 1 && r0 >= 2))
        atomicAdd(&rowsh[r0], accR);
    if (q0)  { atomicAdd(&colsh[0], c0); atomicAdd(&colsh[1], c1); }
    if (q95) { atomicAdd(&colsh[2], c2); atomicAdd(&colsh[3], c3); }

    #pragma unroll
    for (int off = 16; off > 0; off >>= 1)
        tot += __shfl_down_sync(0xffffffffu, tot, off);
    int warp = tid >> 5, lane = tid & 31;
    if (lane == 0) red[warp] = tot;
    __syncthreads();

    if (tid == 0) {
        float T = 0.0f;
        #pragma unroll
        for (int w = 0; w < 12; w++) T += red[w];
        atomicAdd(&g_stat[which][c][0], T);
    }
    if (tid < 4) {
        if (rowsh[tid] != 0.0f) atomicAdd(&g_stat[which][c][1 + tid], rowsh[tid]);
        atomicAdd(&g_stat[which][c][5 + tid], colsh[tid]);
    }
}

// ---------------------------------------------------------------------------
// Finalize: stats -> 9 window sums. grid=2, block=256 (one thread per channel).
// ---------------------------------------------------------------------------
__global__ void __launch_bounds__(256) finalize_kernel() {
    const int which = blockIdx.x;
    const int c = threadIdx.x;
    float a[25];
    #pragma unroll
    for (int j = 0; j < 25; j++) a[j] = g_stat[which][c][j];
    const float T = a[0];
    const int ER[3][2] = { {2,3}, {0,3}, {0,1} };
    float Rex[3] = { a[3]+a[4], a[1]+a[4], a[1]+a[2] };
    float Cex[3] = { a[7]+a[8], a[5]+a[8], a[5]+a[6] };
    #pragma unroll
    for (int kh = 0; kh < 3; kh++) {
        #pragma unroll
        for (int kw = 0; kw < 3; kw++) {
            float cor = 0.0f;
            #pragma unroll
            for (int i = 0; i < 2; i++)
                #pragma unroll
                for (int j = 0; j < 2; j++)
                    cor += a[9 + ER[kh][i]*4 + ER[kw][j]];
            g_S[which][c][kh*3 + kw] = T - Rex[kh] - Cex[kw] + cor;
        }
    }
}

// ---------------------------------------------------------------------------
// Kernel 2: per-output-channel matvec + sigmoid + branch flags -> coefficients.
// ---------------------------------------------------------------------------
__global__ void __launch_bounds__(256) coef_kernel(const float* __restrict__ W,
                                                   const float* __restrict__ b) {
    const int oc = blockIdx.x;
    const int ic = threadIdx.x;
    const float* wrow = W + (size_t)oc * CCH * 9 + ic * 9;
    float d1 = 0.0f, d2 = 0.0f;
    #pragma unroll
    for (int k = 0; k < 9; k++) {
        float w = wrow[k];
        d1 += w * g_S[0][ic][k];
        d2 += w * g_S[1][ic][k];
    }
    #pragma unroll
    for (int off = 16; off > 0; off >>= 1) {
        d1 += __shfl_down_sync(0xffffffffu, d1, off);
        d2 += __shfl_down_sync(0xffffffffu, d2, off);
    }
    __shared__ float s1[8], s2[8];
    int warp = ic >> 5, lane = ic & 31;
    if (lane == 0) { s1[warp] = d1; s2[warp] = d2; }
    __syncthreads();
    if (ic == 0) {
        float D1 = 0.0f, D2 = 0.0f;
        #pragma unroll
        for (int w = 0; w < 8; w++) { D1 += s1[w]; D2 += s2[w]; }
        float bb = b[oc];
        float m1 = bb + D1 * INVN;
        float m2 = bb + D2 * INVN;
        float m3 = bb + (D1 + D2) * INVN;
        float x1 = 1.0f / (1.0f + expf(-m1));
        float x2 = 1.0f / (1.0f + expf(-m2));
        float x3 = 1.0f / (1.0f + expf(-m3));
        bool c1 = (x1 >= x2);
        bool c2 = (x1 <= x2);
        float a1 = (c1 && (x1 >= x3)) ? 1.0f : 0.0f;
        float a2 = (c2 && (x2 >= x3)) ? 1.0f : 0.0f;
        float a3 = ((c1 && (x1 < x3)) || (c2 && (x2 < x3))) ? 1.0f : 0.0f;
        g_cf[0][oc] = a1 + a3;
        g_cf[1][oc] = a2 + a3;
    }
}

// ---------------------------------------------------------------------------
// Kernel 3: out = k1[ch]*in1 + k2[ch]*in2, float4 streaming.
// ---------------------------------------------------------------------------
__global__ void __launch_bounds__(256) combine_kernel(const float4* __restrict__ in1,
                                                      const float4* __restrict__ in2,
                                                      float4* __restrict__ out) {
    const int ch  = blockIdx.x / (NQ / 256);
    const int idx = blockIdx.x * 256 + threadIdx.x;
    const float k1 = g_cf[0][ch];
    const float k2 = g_cf[1][ch];
    float4 a = __ldcs(in1 + idx);
    float4 b = __ldcs(in2 + idx);
    float4 o;
    o.x = k1 * a.x + k2 * b.x;
    o.y = k1 * a.y + k2 * b.y;
    o.z = k1 * a.z + k2 * b.z;
    o.w = k1 * a.w + k2 * b.w;
    __stcs(out + idx, o);
}

extern "C" void kernel_launch(void* const* d_in, const int* in_sizes, int n_in,
                              void* d_out, int out_size) {
    const float* in1 = (const float*)d_in[0];
    const float* in2 = (const float*)d_in[1];
    const float* W   = (const float*)d_in[2];
    const float* b   = (const float*)d_in[3];
    float* out = (float*)d_out;

    init_kernel<<<(2 * CCH * 25 + 255) / 256, 256>>>();
    stats_kernel<<<dim3(CCH, NSEG, 2), 384>>>(in1, in2);
    finalize_kernel<<<2, 256>>>();
    coef_kernel<<<CCH, 256>>>(W, b);
    combine_kernel<<<CCH * (NQ / 256), 256>>>((const float4*)in1,
                                              (const float4*)in2,
                                              (float4*)out);
}

// round 5
// speedup vs baseline: 1.0410x; 1.0410x over previous
#include <cuda_runtime.h>
#include <math.h>

#define CCH   256
#define HW    384
#define NPIX  (HW*HW)        // 147456 elems per channel
#define NQ    (NPIX/4)       // 36864 float4 per channel
#define QPR   (HW/4)         // 96 float4 per row
#define SEGROWS 192
#define SEGQ   (SEGROWS*QPR)              // 18432 float4 per segment
#define ITER   (SEGROWS/3)                // 64 iterations (3-row phase)
#define INVN  (1.0f/(382.0f*382.0f))

// Per-(input, channel, segment) partials, all slots written every launch:
// [0]=total, [1..2]=this segment's two border-row sums,
// [3..6]=col sums (classes 0..3), [7..14]=corners (2 local rows x 4 col classes)
__device__ float g_part[2][CCH][2][15];
__device__ float g_S[2][CCH][9];
__device__ float g_cf[2][CCH];

// ---------------------------------------------------------------------------
// Kernel 1: partial stats. grid = (CCH, 2 segments, 2 inputs), block = 288.
// Threads: r0 = tid/96 in [0,3), q = tid%96. Iteration j covers row
// seg*192 + 3j + r0. Border rows: seg0 j=0 r0<2 (rows 0,1); seg1 j=63 r0>=1
// (rows 382,383). 288 threads @ <=32 regs -> 7 CTAs/SM -> 1036 slots for
// 1024 blocks: single, nearly-full wave.
// ---------------------------------------------------------------------------
__global__ void __launch_bounds__(288, 7) stats_kernel(const float* __restrict__ in1,
                                                       const float* __restrict__ in2) {
    const int c     = blockIdx.x;
    const int seg   = blockIdx.y;
    const int which = blockIdx.z;
    const float4* x = ((const float4*)(which ? in2 : in1))
                      + (size_t)c * NQ + (size_t)seg * SEGQ;

    const int tid = threadIdx.x;
    const int r0  = tid / 96;          // 0..2
    const int q   = tid - r0 * 96;     // 0..95
    const bool q0  = (q == 0);
    const bool q95 = (q == 95);

    __shared__ float rowsh[2];
    __shared__ float colsh[4];
    __shared__ float corn[8];          // [local row class 0/1][col class 0..3]
    __shared__ float red[9];
    if (tid < 2) rowsh[tid] = 0.0f;
    if (tid < 4) colsh[tid] = 0.0f;
    __syncthreads();

    const float4* p = x + (size_t)(r0 * 96 + q);

    float tot = 0.0f;
    float c0 = 0.0f, c1 = 0.0f, c2 = 0.0f, c3 = 0.0f;
    float accR = 0.0f;
    int rowClass = -1;                 // local border-row class (0/1) if owned

    int jstart = 0, jend = ITER;

    if (seg == 0) {
        // peel j=0: rows 0,1,2 -> rows 0,1 are border (r0 < 2)
        float4 v = __ldcs(p);
        float s = (v.x + v.y) + (v.z + v.w);
        tot += s;
        if (q0)  { c0 += v.x; c1 += v.y; }
        if (q95) { c2 += v.z; c3 += v.w; }
        if (r0 < 2) {
            accR = s; rowClass = r0;
            if (q0)  { corn[r0*4 + 0] = v.x; corn[r0*4 + 1] = v.y; }
            if (q95) { corn[r0*4 + 2] = v.z; corn[r0*4 + 3] = v.w; }
        }
        p += 288;
        jstart = 1;
    } else {
        jend = ITER - 1;
    }

    #pragma unroll 4
    for (int j = jstart; j < jend; j++) {
        float4 v = __ldcs(p);
        p += 288;
        tot += (v.x + v.y) + (v.z + v.w);
        if (q0)  { c0 += v.x; c1 += v.y; }
        if (q95) { c2 += v.z; c3 += v.w; }
    }

    if (seg == 1) {
        // peel j=63: rows 381,382,383 -> rows 382 (r0=1), 383 (r0=2) are border
        float4 v = __ldcs(p);
        float s = (v.x + v.y) + (v.z + v.w);
        tot += s;
        if (q0)  { c0 += v.x; c1 += v.y; }
        if (q95) { c2 += v.z; c3 += v.w; }
        if (r0 >= 1) {
            int lc = r0 - 1;           // local class 0 -> row 382, 1 -> row 383
            accR = s; rowClass = lc;
            if (q0)  { corn[lc*4 + 0] = v.x; corn[lc*4 + 1] = v.y; }
            if (q95) { corn[lc*4 + 2] = v.z; corn[lc*4 + 3] = v.w; }
        }
    }

    // block reductions (shared atomics for the sparse stats)
    if (rowClass >= 0) atomicAdd(&rowsh[rowClass], accR);
    if (q0)  { atomicAdd(&colsh[0], c0); atomicAdd(&colsh[1], c1); }
    if (q95) { atomicAdd(&colsh[2], c2); atomicAdd(&colsh[3], c3); }

    #pragma unroll
    for (int off = 16; off > 0; off >>= 1)
        tot += __shfl_down_sync(0xffffffffu, tot, off);
    int warp = tid >> 5, lane = tid & 31;
    if (lane == 0) red[warp] = tot;
    __syncthreads();

    if (tid == 0) {
        float T = 0.0f;
        #pragma unroll
        for (int w = 0; w < 9; w++) T += red[w];
        float* d = g_part[which][c][seg];
        d[0] = T;
        d[1] = rowsh[0]; d[2] = rowsh[1];
        d[3] = colsh[0]; d[4] = colsh[1]; d[5] = colsh[2]; d[6] = colsh[3];
        #pragma unroll
        for (int k = 0; k < 8; k++) d[7 + k] = corn[k];
    }
}

// ---------------------------------------------------------------------------
// Finalize: merge 2 segments -> 9 window sums. grid=2, block=256.
// ---------------------------------------------------------------------------
__global__ void __launch_bounds__(256) finalize_kernel() {
    const int which = blockIdx.x;
    const int c = threadIdx.x;
    const float* p0 = g_part[which][c][0];
    const float* p1 = g_part[which][c][1];

    float T = p0[0] + p1[0];
    float rs[4] = { p0[1], p0[2], p1[1], p1[2] };        // rows 0,1,382,383
    float cs[4];
    #pragma unroll
    for (int k = 0; k < 4; k++) cs[k] = p0[3 + k] + p1[3 + k];
    float corn[16];                                       // [row class][col class]
    #pragma unroll
    for (int k = 0; k < 8; k++) { corn[k] = p0[7 + k]; corn[8 + k] = p1[7 + k]; }

    const int ER[3][2] = { {2,3}, {0,3}, {0,1} };
    float Rex[3] = { rs[2]+rs[3], rs[0]+rs[3], rs[0]+rs[1] };
    float Cex[3] = { cs[2]+cs[3], cs[0]+cs[3], cs[0]+cs[1] };
    #pragma unroll
    for (int kh = 0; kh < 3; kh++) {
        #pragma unroll
        for (int kw = 0; kw < 3; kw++) {
            float cor = 0.0f;
            #pragma unroll
            for (int i = 0; i < 2; i++)
                #pragma unroll
                for (int j = 0; j < 2; j++)
                    cor += corn[ER[kh][i]*4 + ER[kw][j]];
            g_S[which][c][kh*3 + kw] = T - Rex[kh] - Cex[kw] + cor;
        }
    }
}

// ---------------------------------------------------------------------------
// Kernel 2: per-output-channel matvec + sigmoid + branch flags -> coefficients.
// ---------------------------------------------------------------------------
__global__ void __launch_bounds__(256) coef_kernel(const float* __restrict__ W,
                                                   const float* __restrict__ b) {
    const int oc = blockIdx.x;
    const int ic = threadIdx.x;
    const float* wrow = W + (size_t)oc * CCH * 9 + ic * 9;
    float d1 = 0.0f, d2 = 0.0f;
    #pragma unroll
    for (int k = 0; k < 9; k++) {
        float w = wrow[k];
        d1 += w * g_S[0][ic][k];
        d2 += w * g_S[1][ic][k];
    }
    #pragma unroll
    for (int off = 16; off > 0; off >>= 1) {
        d1 += __shfl_down_sync(0xffffffffu, d1, off);
        d2 += __shfl_down_sync(0xffffffffu, d2, off);
    }
    __shared__ float s1[8], s2[8];
    int warp = ic >> 5, lane = ic & 31;
    if (lane == 0) { s1[warp] = d1; s2[warp] = d2; }
    __syncthreads();
    if (ic == 0) {
        float D1 = 0.0f, D2 = 0.0f;
        #pragma unroll
        for (int w = 0; w < 8; w++) { D1 += s1[w]; D2 += s2[w]; }
        float bb = b[oc];
        float m1 = bb + D1 * INVN;
        float m2 = bb + D2 * INVN;
        float m3 = bb + (D1 + D2) * INVN;
        float x1 = 1.0f / (1.0f + expf(-m1));
        float x2 = 1.0f / (1.0f + expf(-m2));
        float x3 = 1.0f / (1.0f + expf(-m3));
        bool c1 = (x1 >= x2);
        bool c2 = (x1 <= x2);
        float a1 = (c1 && (x1 >= x3)) ? 1.0f : 0.0f;
        float a2 = (c2 && (x2 >= x3)) ? 1.0f : 0.0f;
        float a3 = ((c1 && (x1 < x3)) || (c2 && (x2 < x3))) ? 1.0f : 0.0f;
        g_cf[0][oc] = a1 + a3;
        g_cf[1][oc] = a2 + a3;
    }
}

// ---------------------------------------------------------------------------
// Kernel 3: out = k1[ch]*in1 + k2[ch]*in2, float4 streaming (at HBM peak).
// ---------------------------------------------------------------------------
__global__ void __launch_bounds__(256) combine_kernel(const float4* __restrict__ in1,
                                                      const float4* __restrict__ in2,
                                                      float4* __restrict__ out) {
    const int ch  = blockIdx.x / (NQ / 256);
    const int idx = blockIdx.x * 256 + threadIdx.x;
    const float k1 = g_cf[0][ch];
    const float k2 = g_cf[1][ch];
    float4 a = __ldcs(in1 + idx);
    float4 b = __ldcs(in2 + idx);
    float4 o;
    o.x = k1 * a.x + k2 * b.x;
    o.y = k1 * a.y + k2 * b.y;
    o.z = k1 * a.z + k2 * b.z;
    o.w = k1 * a.w + k2 * b.w;
    __stcs(out + idx, o);
}

extern "C" void kernel_launch(void* const* d_in, const int* in_sizes, int n_in,
                              void* d_out, int out_size) {
    const float* in1 = (const float*)d_in[0];
    const float* in2 = (const float*)d_in[1];
    const float* W   = (const float*)d_in[2];
    const float* b   = (const float*)d_in[3];
    float* out = (float*)d_out;

    stats_kernel<<<dim3(CCH, 2, 2), 288>>>(in1, in2);
    finalize_kernel<<<2, 256>>>();
    coef_kernel<<<CCH, 256>>>(W, b);
    combine_kernel<<<CCH * (NQ / 256), 256>>>((const float4*)in1,
                                              (const float4*)in2,
                                              (float4*)out);
}